// round 11
// baseline (speedup 1.0000x reference)
#include <cuda_runtime.h>
#include <cstdint>

#define NC     16
#define CS     32
#define NH     16
#define NF     512
#define BATCH  131072
#define RROWS  32          // rows per block
#define THREADS 256
#define TSTRIDE 516        // padded tile row stride (floats)
#define BSTRIDE 36         // bounce buffer row stride (floats)
#define TILE_F  (RROWS * TSTRIDE)            // 16512 floats
#define BOUNCE_F (32 * BSTRIDE)              // 1152 floats per warp

// W lives in constant memory: warp-uniform reads go through LDCU (uniform
// pipe), bypassing the L1 crossbar entirely. 16*32*32*4 = 64KB = the limit.
__constant__ float c_W[NC * CS * CS];

__device__ float g_Wstage[NC * CS * CS];
__device__ float g_bias[NC * CS];
__device__ int   g_pos[NF];

__global__ void prep_kernel(const float* __restrict__ enc_w,
                            const float* __restrict__ enc_b,
                            const float* __restrict__ dec_w,
                            const float* __restrict__ dec_b,
                            const int*   __restrict__ clusters) {
    int t = blockIdx.x * blockDim.x + threadIdx.x;
    if (t < NC * CS * CS) {
        int n = t >> 10;
        int c = (t >> 5) & 31;
        int k = t & 31;
        const float* dw = dec_w + (n * CS + c) * NH;
        const float* ew = enc_w + n * NH * CS + k;
        float s = 0.f;
#pragma unroll
        for (int h = 0; h < NH; h++) s += dw[h] * ew[h * CS];
        g_Wstage[t] = s;
    }
    if (t < NC * CS) {
        int n = t >> 5;
        const float* dw = dec_w + t * NH;
        const float* eb = enc_b + n * NH;
        float s = dec_b[t];
#pragma unroll
        for (int h = 0; h < NH; h++) s += dw[h] * eb[h];
        g_bias[t] = s;
        g_pos[clusters[t]] = t;
    }
}

// Lane = batch row. Warp w handles rows 0..31 of the tile for clusters
// {2w, 2w+1}. Each lane reads its row's gathered 128B segment ONCE (8
// conflict-free LDS.128), streams W from constant memory (uniform), and
// accumulates 32 outputs in two 16-output halves. Outputs bounce through a
// per-warp padded smem buffer so stores are coalesced (4 rows x 8 chunks).
__global__ void __launch_bounds__(THREADS, 2)
ensemble_kernel(const float* __restrict__ x, float* __restrict__ y) {
    extern __shared__ __align__(16) float smem[];
    float* tile = smem;                                // TILE_F floats
    const int tid  = threadIdx.x;
    const int warp = tid >> 5;
    const int lane = tid & 31;
    float* buf = smem + TILE_F + warp * BOUNCE_F;      // 32 x 36 per warp
    const long long row0 = (long long)blockIdx.x * RROWS;

    // ---- scatter phase: coalesced read, permuted write into tile ----
    {
        const float4* xv = (const float4*)(x) + row0 * (NF / 4);
        const int4*   pv = (const int4*)g_pos;
#pragma unroll 4
        for (int i = 0; i < (RROWS * NF / 4) / THREADS; i++) {
            int idx = tid + i * THREADS;
            int r   = idx >> 7;
            int f4  = idx & 127;
            float4 v = xv[idx];
            int4   p = pv[f4];
            float* dst = tile + r * TSTRIDE;
            dst[p.x] = v.x;
            dst[p.y] = v.y;
            dst[p.z] = v.z;
            dst[p.w] = v.w;
        }
    }
    __syncthreads();

    const int rg = lane >> 3;        // drain: row group 0..3
    const int q  = lane & 7;         // drain: 16B chunk 0..7

#pragma unroll 1
    for (int ci = 0; ci < 2; ci++) {
        const int cl = warp * 2 + ci;

        // ---- x: this lane's row segment, once, as 16 packed f32 pairs ----
        ulonglong2 xv[8];
        {
            const float* src = tile + lane * TSTRIDE + cl * CS;
#pragma unroll
            for (int i = 0; i < 8; i++)
                xv[i] = *(const ulonglong2*)(src + i * 4);
        }

        // ---- two halves of 16 outputs each ----
#pragma unroll 1
        for (int h = 0; h < 2; h++) {
            unsigned long long acc[16];
            const float* wbase = c_W + cl * (CS * CS) + h * (16 * CS);
#pragma unroll
            for (int c = 0; c < 16; c++) {
                const ulonglong2* wp = (const ulonglong2*)(wbase + c * CS);
#pragma unroll
                for (int j = 0; j < 8; j++) {
                    ulonglong2 wv = wp[j];
                    if (j == 0) {
                        asm("mul.rn.f32x2 %0,%1,%2;"
                            : "=l"(acc[c]) : "l"(wv.x), "l"(xv[0].x));
                    } else {
                        asm("fma.rn.f32x2 %0,%1,%2,%0;"
                            : "+l"(acc[c]) : "l"(wv.x), "l"(xv[j].x));
                    }
                    asm("fma.rn.f32x2 %0,%1,%2,%0;"
                        : "+l"(acc[c]) : "l"(wv.y), "l"(xv[j].y));
                }
            }
            // fold + bias, pack 4, store to bounce buffer (conflict-free)
#pragma unroll
            for (int g = 0; g < 4; g++) {
                float4 bv = *(const float4*)(g_bias + cl * CS + h * 16 + g * 4);
                float4 o;
                uint32_t lo, hi;
                asm("mov.b64 {%0,%1},%2;" : "=r"(lo), "=r"(hi) : "l"(acc[4 * g + 0]));
                o.x = __uint_as_float(lo) + __uint_as_float(hi) + bv.x;
                asm("mov.b64 {%0,%1},%2;" : "=r"(lo), "=r"(hi) : "l"(acc[4 * g + 1]));
                o.y = __uint_as_float(lo) + __uint_as_float(hi) + bv.y;
                asm("mov.b64 {%0,%1},%2;" : "=r"(lo), "=r"(hi) : "l"(acc[4 * g + 2]));
                o.z = __uint_as_float(lo) + __uint_as_float(hi) + bv.z;
                asm("mov.b64 {%0,%1},%2;" : "=r"(lo), "=r"(hi) : "l"(acc[4 * g + 3]));
                o.w = __uint_as_float(lo) + __uint_as_float(hi) + bv.w;
                *(float4*)(buf + lane * BSTRIDE + h * 16 + g * 4) = o;
            }
        }
        __syncwarp();

        // ---- drain: coalesced stores, 4 rows x 8 chunks per instruction ----
        {
            float* ybase = y + row0 * NF + cl * CS;
#pragma unroll
            for (int i = 0; i < 8; i++) {
                int row = rg + 4 * i;
                float4 v = *(const float4*)(buf + row * BSTRIDE + q * 4);
                *(float4*)(ybase + (size_t)row * NF + q * 4) = v;
            }
        }
        __syncwarp();   // buf reused by next cluster
    }
}

extern "C" void kernel_launch(void* const* d_in, const int* in_sizes, int n_in,
                              void* d_out, int out_size) {
    const float* x        = (const float*)d_in[0];
    const int*   clusters = (const int*)  d_in[1];
    const float* enc_w    = (const float*)d_in[2];
    const float* enc_b    = (const float*)d_in[3];
    const float* dec_w    = (const float*)d_in[4];
    const float* dec_b    = (const float*)d_in[5];
    float*       y        = (float*)d_out;

    const int smem_bytes = (TILE_F + 8 * BOUNCE_F) * sizeof(float);  // 102912
    static int smem_set = 0;
    if (!smem_set) {
        cudaFuncSetAttribute(ensemble_kernel,
                             cudaFuncAttributeMaxDynamicSharedMemorySize, smem_bytes);
        smem_set = 1;
    }

    prep_kernel<<<32, 512>>>(enc_w, enc_b, dec_w, dec_b, clusters);

    // Copy fused W into constant memory (D2D async memcpy: graph-capturable).
    void* wstage = nullptr;
    cudaGetSymbolAddress(&wstage, g_Wstage);
    cudaMemcpyToSymbolAsync(c_W, wstage, NC * CS * CS * sizeof(float), 0,
                            cudaMemcpyDeviceToDevice, 0);

    ensemble_kernel<<<BATCH / RROWS, THREADS, smem_bytes>>>(x, y);
}

// round 15
// speedup vs baseline: 6.8908x; 6.8908x over previous
#include <cuda_runtime.h>
#include <cuda_fp16.h>
#include <cstdint>

#define NC 16
#define CS 32
#define NH 16
#define NF 512
#define BATCH 131072
#define MROWS 128
#define THREADS 256

#define AS_BYTES 1040                  // A row stride: 1040 % 128 = 16 -> ldmatrix conflict-free
#define WS_BYTES 80                    // W row stride: 80*r % 128 distinct for r=0..7
#define WCL_BYTES (CS * WS_BYTES)      // 2560 per cluster
#define SM_A  0
#define SM_WH (MROWS * AS_BYTES)               // 133120
#define SM_WL (SM_WH + NC * WCL_BYTES)         // 174080
#define SM_TOTAL (SM_WL + NC * WCL_BYTES)      // 215040

__device__ float  g_bias[NC * CS];
__device__ int    g_pos[NF];           // pos[feature] = cl*32 + k
__device__ __half g_Wh[NC * CS * CS];  // hi half of fused W[cl][c][k]
__device__ __half g_Wl[NC * CS * CS];  // lo half (W - Wh)

__global__ void prep_kernel(const float* __restrict__ enc_w,
                            const float* __restrict__ enc_b,
                            const float* __restrict__ dec_w,
                            const float* __restrict__ dec_b,
                            const int*   __restrict__ clusters) {
    int t = blockIdx.x * blockDim.x + threadIdx.x;
    if (t < NC * CS * CS) {
        int n = t >> 10, c = (t >> 5) & 31, k = t & 31;
        const float* dw = dec_w + (n * CS + c) * NH;
        const float* ew = enc_w + n * NH * CS + k;
        float s = 0.f;
        for (int h = 0; h < NH; h++) s += dw[h] * ew[h * CS];
        __half hh = __float2half_rn(s);
        g_Wh[t] = hh;
        g_Wl[t] = __float2half_rn(s - __half2float(hh));
    }
    if (t < NC * CS) {
        int n = t >> 5;
        const float* dw = dec_w + t * NH;
        const float* eb = enc_b + n * NH;
        float s = dec_b[t];
        for (int h = 0; h < NH; h++) s += dw[h] * eb[h];
        g_bias[t] = s;
        g_pos[clusters[t]] = t;
    }
}

__device__ __forceinline__ void mma_16816(float* acc, const uint32_t* A,
                                          const uint32_t* B) {
    asm volatile("mma.sync.aligned.m16n8k16.row.col.f32.f16.f16.f32 "
                 "{%0,%1,%2,%3},{%4,%5,%6,%7},{%8,%9},{%0,%1,%2,%3};"
                 : "+f"(acc[0]), "+f"(acc[1]), "+f"(acc[2]), "+f"(acc[3])
                 : "r"(A[0]), "r"(A[1]), "r"(A[2]), "r"(A[3]),
                   "r"(B[0]), "r"(B[1]));
}
__device__ __forceinline__ void ldsm4(uint32_t* R, uint32_t addr) {
    asm volatile("ldmatrix.sync.aligned.m8n8.x4.shared.b16 {%0,%1,%2,%3},[%4];"
                 : "=r"(R[0]), "=r"(R[1]), "=r"(R[2]), "=r"(R[3]) : "r"(addr));
}
__device__ __forceinline__ void ldsm2(uint32_t* R, uint32_t addr) {
    asm volatile("ldmatrix.sync.aligned.m8n8.x2.shared.b16 {%0,%1},[%2];"
                 : "=r"(R[0]), "=r"(R[1]) : "r"(addr));
}

// Warp w handles clusters {2w, 2w+1} (y cols 64w..64w+63) for all 8 m-tiles.
// A fp16 in smem (row stride 1040B), W hi/lo fragments register-stationary.
// y_tile = Ah*Wh + Ah*Wl accumulated in fp32 by HMMA.
__global__ void __launch_bounds__(THREADS, 1)
ensemble_kernel(const float* __restrict__ x, float* __restrict__ y) {
    extern __shared__ __align__(16) char smem[];
    uint32_t sb;
    asm("{ .reg .u64 t0; cvta.to.shared.u64 t0, %1; cvt.u32.u64 %0, t0; }"
        : "=r"(sb) : "l"(smem));
    const int tid  = threadIdx.x;
    const int warp = tid >> 5;
    const int lane = tid & 31;
    const long long row0 = (long long)blockIdx.x * MROWS;

    // ---- W hi/lo -> smem (16B chunks, conflict-free) ----
    {
        const uint4* wh = (const uint4*)g_Wh;   // 8 halves per uint4
        const uint4* wl = (const uint4*)g_Wl;
        for (int i = tid; i < NC * CS * CS / 8; i += THREADS) {
            int cl = i >> 7;
            int c  = (i >> 2) & 31;
            int kg = i & 3;
            int off = cl * WCL_BYTES + c * WS_BYTES + kg * 16;
            *(uint4*)(smem + SM_WH + off) = wh[i];
            *(uint4*)(smem + SM_WL + off) = wl[i];
        }
    }

    // ---- scatter x -> A tile (fp16, gathered order; byte off = 2*pos) ----
    {
        const float4* xv = (const float4*)x + row0 * (NF / 4);
        const int4*   pv = (const int4*)g_pos;
        for (int idx = tid; idx < MROWS * NF / 4; idx += THREADS) {
            int r  = idx >> 7;
            int f4 = idx & 127;
            float4 v = xv[idx];
            int4   p = pv[f4];
            char* base = smem + SM_A + r * AS_BYTES;
            *(__half*)(base + p.x * 2) = __float2half_rn(v.x);
            *(__half*)(base + p.y * 2) = __float2half_rn(v.y);
            *(__half*)(base + p.z * 2) = __float2half_rn(v.z);
            *(__half*)(base + p.w * 2) = __float2half_rn(v.w);
        }
    }
    __syncthreads();

    // ---- stationary B fragments: bh/bl[ci][ntile][kstep][2] ----
    // b frag (k16 x n8): lane l holds W[cl][n=l/4][k=2(l%4)+{0,1}(+8)]
    // = non-trans ldmatrix.x2 on W rows (lanes 0-7: +0B, 8-15: +16B).
    uint32_t bh[2][4][2][2], bl[2][4][2][2];
    {
        const int wrow = (lane & 7) * WS_BYTES + ((lane >> 3) & 1) * 16;
#pragma unroll
        for (int ci = 0; ci < 2; ci++) {
            int cl = warp * 2 + ci;
#pragma unroll
            for (int t = 0; t < 4; t++) {
#pragma unroll
                for (int s = 0; s < 2; s++) {
                    int off = cl * WCL_BYTES + t * 8 * WS_BYTES + s * 32 + wrow;
                    ldsm2(bh[ci][t][s], sb + SM_WH + off);
                    ldsm2(bl[ci][t][s], sb + SM_WL + off);
                }
            }
        }
    }

    float2 bias[2][4];
#pragma unroll
    for (int ci = 0; ci < 2; ci++) {
#pragma unroll
        for (int t = 0; t < 4; t++) {
            bias[ci][t] = *(const float2*)(g_bias + (warp * 2 + ci) * CS
                                           + t * 8 + 2 * (lane & 3));
        }
    }

    // A-frag lane address component (x4: rows l&7 (+8 via bit3), +16B via bit4)
    const int arow = ((lane & 7) + ((lane >> 3) & 1) * 8) * AS_BYTES
                   + ((lane >> 4) & 1) * 16;

    for (int m = 0; m < MROWS / 16; m++) {
        uint32_t a[2][2][4];
#pragma unroll
        for (int ci = 0; ci < 2; ci++) {
#pragma unroll
            for (int s = 0; s < 2; s++) {
                int addr = m * 16 * AS_BYTES + (warp * 2 + ci) * 64 + s * 32 + arow;
                ldsm4(a[ci][s], sb + SM_A + addr);
            }
        }

        float acc[2][4][4];
#pragma unroll
        for (int ci = 0; ci < 2; ci++) {
#pragma unroll
            for (int t = 0; t < 4; t++) {
                acc[ci][t][0] = 0.f; acc[ci][t][1] = 0.f;
                acc[ci][t][2] = 0.f; acc[ci][t][3] = 0.f;
                mma_16816(acc[ci][t], a[ci][0], bh[ci][t][0]);
                mma_16816(acc[ci][t], a[ci][1], bh[ci][t][1]);
                mma_16816(acc[ci][t], a[ci][0], bl[ci][t][0]);
                mma_16816(acc[ci][t], a[ci][1], bl[ci][t][1]);
            }
        }

        // epilogue: c frag rows l/4, l/4+8; cols 2(l%4)+{0,1}
        const long long rlo = row0 + m * 16 + (lane >> 2);
#pragma unroll
        for (int ci = 0; ci < 2; ci++) {
#pragma unroll
            for (int t = 0; t < 4; t++) {
                int col = warp * 64 + ci * 32 + t * 8 + 2 * (lane & 3);
                float2 o0, o1;
                o0.x = acc[ci][t][0] + bias[ci][t].x;
                o0.y = acc[ci][t][1] + bias[ci][t].y;
                o1.x = acc[ci][t][2] + bias[ci][t].x;
                o1.y = acc[ci][t][3] + bias[ci][t].y;
                *(float2*)(y + rlo * NF + col)       = o0;
                *(float2*)(y + (rlo + 8) * NF + col) = o1;
            }
        }
    }
}

extern "C" void kernel_launch(void* const* d_in, const int* in_sizes, int n_in,
                              void* d_out, int out_size) {
    const float* x        = (const float*)d_in[0];
    const int*   clusters = (const int*)  d_in[1];
    const float* enc_w    = (const float*)d_in[2];
    const float* enc_b    = (const float*)d_in[3];
    const float* dec_w    = (const float*)d_in[4];
    const float* dec_b    = (const float*)d_in[5];
    float*       y        = (float*)d_out;

    static int attr_set = 0;
    if (!attr_set) {
        cudaFuncSetAttribute(ensemble_kernel,
                             cudaFuncAttributeMaxDynamicSharedMemorySize, SM_TOTAL);
        attr_set = 1;
    }

    prep_kernel<<<32, 512>>>(enc_w, enc_b, dec_w, dec_b, clusters);
    ensemble_kernel<<<BATCH / MROWS, THREADS, SM_TOTAL>>>(x, y);
}

// round 16
// speedup vs baseline: 9.3773x; 1.3608x over previous
#include <cuda_runtime.h>
#include <cuda_fp16.h>
#include <cstdint>

#define NC 16
#define CS 32
#define NH 16
#define NF 512
#define BATCH 131072
#define MROWS 64
#define THREADS 256

#define AS_BYTES 1040                  // A row stride: 1040 % 128 = 16 -> ldmatrix conflict-free
#define SM_TOTAL (MROWS * AS_BYTES)    // 66560 bytes: A tile only -> 2 CTAs/SM

__device__ float    g_bias[NC * CS];
__device__ int      g_pos[NF];            // pos[feature] = cl*32 + k
__device__ __half   g_Wh[NC * CS * CS];   // hi half of fused W[cl][c][k]
__device__ __half   g_Wl[NC * CS * CS];   // lo half (W - Wh)
// Fragment-order W table: idx = ((((cl*4+t)*2+s)*2+hl)*2+reg)*32+lane.
// Each u32 = the exact 2-half operand lane `lane` needs for mma B-frag
// (t = n-tile, s = k-step, hl = hi/lo, reg = k or k+8).
__device__ uint32_t g_Wfrag[NC * 4 * 2 * 2 * 2 * 32];

__global__ void prep_kernel(const float* __restrict__ enc_w,
                            const float* __restrict__ enc_b,
                            const float* __restrict__ dec_w,
                            const float* __restrict__ dec_b,
                            const int*   __restrict__ clusters) {
    int t = blockIdx.x * blockDim.x + threadIdx.x;
    if (t < NC * CS * CS) {
        int n = t >> 10, c = (t >> 5) & 31, k = t & 31;
        const float* dw = dec_w + (n * CS + c) * NH;
        const float* ew = enc_w + n * NH * CS + k;
        float s = 0.f;
        for (int h = 0; h < NH; h++) s += dw[h] * ew[h * CS];
        __half hh = __float2half_rn(s);
        g_Wh[t] = hh;
        g_Wl[t] = __float2half_rn(s - __half2float(hh));
    }
    if (t < NC * CS) {
        int n = t >> 5;
        const float* dw = dec_w + t * NH;
        const float* eb = enc_b + n * NH;
        float s = dec_b[t];
        for (int h = 0; h < NH; h++) s += dw[h] * eb[h];
        g_bias[t] = s;
        g_pos[clusters[t]] = t;
    }
}

// Build fragment-order W table (runs after prep_kernel).
__global__ void prep2_kernel() {
    int i = blockIdx.x * blockDim.x + threadIdx.x;   // 16384 entries
    if (i >= NC * 4 * 2 * 2 * 2 * 32) return;
    int lane = i & 31;
    int reg  = (i >> 5) & 1;
    int hl   = (i >> 6) & 1;
    int s    = (i >> 7) & 1;
    int t    = (i >> 8) & 3;
    int cl   = i >> 10;
    int c = t * 8 + (lane >> 2);                     // n index
    int k = s * 16 + 2 * (lane & 3) + reg * 8;
    const __half* src = hl ? g_Wl : g_Wh;
    g_Wfrag[i] = *(const uint32_t*)(src + cl * (CS * CS) + c * CS + k);
}

__device__ __forceinline__ void mma_16816(float* acc, const uint32_t* A,
                                          const uint32_t* B) {
    asm volatile("mma.sync.aligned.m16n8k16.row.col.f32.f16.f16.f32 "
                 "{%0,%1,%2,%3},{%4,%5,%6,%7},{%8,%9},{%0,%1,%2,%3};"
                 : "+f"(acc[0]), "+f"(acc[1]), "+f"(acc[2]), "+f"(acc[3])
                 : "r"(A[0]), "r"(A[1]), "r"(A[2]), "r"(A[3]),
                   "r"(B[0]), "r"(B[1]));
}
__device__ __forceinline__ void ldsm4(uint32_t* R, uint32_t addr) {
    asm volatile("ldmatrix.sync.aligned.m8n8.x4.shared.b16 {%0,%1,%2,%3},[%4];"
                 : "=r"(R[0]), "=r"(R[1]), "=r"(R[2]), "=r"(R[3]) : "r"(addr));
}

// 64-row tile, 2 CTAs/SM. Warp w: clusters {2w, 2w+1}, all 4 m-tiles.
// W fragments register-stationary, loaded coalesced from g_Wfrag (L2-hot).
__global__ void __launch_bounds__(THREADS, 2)
ensemble_kernel(const float* __restrict__ x, float* __restrict__ y) {
    extern __shared__ __align__(16) char smem[];
    uint32_t sb;
    asm("{ .reg .u64 t0; cvta.to.shared.u64 t0, %1; cvt.u32.u64 %0, t0; }"
        : "=r"(sb) : "l"(smem));
    const int tid  = threadIdx.x;
    const int warp = tid >> 5;
    const int lane = tid & 31;
    const long long row0 = (long long)blockIdx.x * MROWS;

    // ---- stationary B fragments straight from global (coalesced, L2-hot).
    // Issued first so their latency overlaps the scatter's LDGs.
    uint32_t bh[2][4][2][2], bl[2][4][2][2];
#pragma unroll
    for (int ci = 0; ci < 2; ci++) {
        int cl = warp * 2 + ci;
#pragma unroll
        for (int t = 0; t < 4; t++) {
#pragma unroll
            for (int s = 0; s < 2; s++) {
                int base = (((cl * 4 + t) * 2 + s) * 2) * 2 * 32 + lane;
                bh[ci][t][s][0] = g_Wfrag[base];
                bh[ci][t][s][1] = g_Wfrag[base + 32];
                bl[ci][t][s][0] = g_Wfrag[base + 64];
                bl[ci][t][s][1] = g_Wfrag[base + 96];
            }
        }
    }

    // ---- scatter x -> A tile (fp16, gathered order; byte off = 2*pos) ----
    {
        const float4* xv = (const float4*)x + row0 * (NF / 4);
        const int4*   pv = (const int4*)g_pos;
        for (int idx = tid; idx < MROWS * NF / 4; idx += THREADS) {
            int r  = idx >> 7;
            int f4 = idx & 127;
            float4 v = xv[idx];
            int4   p = pv[f4];
            char* base = smem + r * AS_BYTES;
            *(__half*)(base + p.x * 2) = __float2half_rn(v.x);
            *(__half*)(base + p.y * 2) = __float2half_rn(v.y);
            *(__half*)(base + p.z * 2) = __float2half_rn(v.z);
            *(__half*)(base + p.w * 2) = __float2half_rn(v.w);
        }
    }
    __syncthreads();

    // A-frag lane address component (x4: rows l&7 (+8 via bit3), +16B via bit4)
    const int arow = ((lane & 7) + ((lane >> 3) & 1) * 8) * AS_BYTES
                   + ((lane >> 4) & 1) * 16;

    for (int m = 0; m < MROWS / 16; m++) {
        float acc[2][4][4];
#pragma unroll
        for (int ci = 0; ci < 2; ci++) {
            uint32_t a[2][4];
#pragma unroll
            for (int s = 0; s < 2; s++) {
                int addr = m * 16 * AS_BYTES + (warp * 2 + ci) * 64 + s * 32 + arow;
                ldsm4(a[s], sb + addr);
            }
#pragma unroll
            for (int t = 0; t < 4; t++) {
                acc[ci][t][0] = 0.f; acc[ci][t][1] = 0.f;
                acc[ci][t][2] = 0.f; acc[ci][t][3] = 0.f;
                mma_16816(acc[ci][t], a[0], bh[ci][t][0]);
                mma_16816(acc[ci][t], a[1], bh[ci][t][1]);
                mma_16816(acc[ci][t], a[0], bl[ci][t][0]);
                mma_16816(acc[ci][t], a[1], bl[ci][t][1]);
            }
        }

        // epilogue: c frag rows l/4, l/4+8; cols 2(l%4)+{0,1}
        const long long rlo = row0 + m * 16 + (lane >> 2);
#pragma unroll
        for (int ci = 0; ci < 2; ci++) {
#pragma unroll
            for (int t = 0; t < 4; t++) {
                int col = warp * 64 + ci * 32 + t * 8 + 2 * (lane & 3);
                float2 bv = __ldg((const float2*)(g_bias + col));
                float2 o0, o1;
                o0.x = acc[ci][t][0] + bv.x;
                o0.y = acc[ci][t][1] + bv.y;
                o1.x = acc[ci][t][2] + bv.x;
                o1.y = acc[ci][t][3] + bv.y;
                *(float2*)(y + rlo * NF + col)       = o0;
                *(float2*)(y + (rlo + 8) * NF + col) = o1;
            }
        }
    }
}

extern "C" void kernel_launch(void* const* d_in, const int* in_sizes, int n_in,
                              void* d_out, int out_size) {
    const float* x        = (const float*)d_in[0];
    const int*   clusters = (const int*)  d_in[1];
    const float* enc_w    = (const float*)d_in[2];
    const float* enc_b    = (const float*)d_in[3];
    const float* dec_w    = (const float*)d_in[4];
    const float* dec_b    = (const float*)d_in[5];
    float*       y        = (float*)d_out;

    static int attr_set = 0;
    if (!attr_set) {
        cudaFuncSetAttribute(ensemble_kernel,
                             cudaFuncAttributeMaxDynamicSharedMemorySize, SM_TOTAL);
        attr_set = 1;
    }

    prep_kernel<<<32, 512>>>(enc_w, enc_b, dec_w, dec_b, clusters);
    prep2_kernel<<<32, 512>>>();
    ensemble_kernel<<<BATCH / MROWS, THREADS, SM_TOTAL>>>(x, y);
}